// round 13
// baseline (speedup 1.0000x reference)
#include <cuda_runtime.h>
#include <cuda_bf16.h>
#include <math.h>

#define E_MAX 32768
#define NSTRIPES 18

// ---------------- device scratch (allocation-free) -------------------------
// A images: per 32-edge tile, 32 rows x 256 B ([xh(64k)|xl(64k)] bf16, chunk-XOR swizzled)
__device__ unsigned g_aimg[(E_MAX / 32) * 2048];
// tmp fp32, m-major per edge: g_tmp[e*288 + m*96 + j]
__device__ float g_tmp[(size_t)E_MAX * 288];
// B images: per 384-col slab, 384 rows x 256 B ([wh|wl], swizzled)
__device__ unsigned char g_b[8 * 98304];

__device__ __forceinline__ float gelu_exact(float v) {
    return 0.5f * v * (1.0f + erff(v * 0.70710678118654752440f));
}
__device__ __forceinline__ unsigned smem_u32(const void* p) {
    return (unsigned)__cvta_generic_to_shared(p);
}
__device__ __forceinline__ void cp16(void* sdst, const void* gsrc) {
    asm volatile("cp.async.cg.shared.global [%0], [%1], 16;"
                 :: "r"(smem_u32(sdst)), "l"(gsrc));
}
__device__ __forceinline__ void cp_commit() { asm volatile("cp.async.commit_group;"); }
template <int N> __device__ __forceinline__ void cp_wait() {
    asm volatile("cp.async.wait_group %0;" :: "n"(N));
}

// ---- warp MMA primitives (baseline PTX: sm_80+, compiles for sm_103) ------
__device__ __forceinline__ void ldsm4(unsigned* r, unsigned addr) {
    asm volatile("ldmatrix.sync.aligned.m8n8.x4.shared.b16 {%0,%1,%2,%3}, [%4];"
        : "=r"(r[0]), "=r"(r[1]), "=r"(r[2]), "=r"(r[3]) : "r"(addr));
}
__device__ __forceinline__ void mma16816(float* d, const unsigned* a,
                                         const unsigned* b) {
    asm volatile("mma.sync.aligned.m16n8k16.row.col.f32.bf16.bf16.f32 "
        "{%0,%1,%2,%3}, {%4,%5,%6,%7}, {%8,%9}, {%0,%1,%2,%3};"
        : "+f"(d[0]), "+f"(d[1]), "+f"(d[2]), "+f"(d[3])
        : "r"(a[0]), "r"(a[1]), "r"(a[2]), "r"(a[3]), "r"(b[0]), "r"(b[1]));
}

// ---------------------------------------------------------------------------
// Kernel 1: MLP (Linear->LN->GELU)x2 -> bf16-split swizzled A image;
//           tmp = feats@basis -> fp32 m-major.  (unchanged from R11/R12)
// ---------------------------------------------------------------------------
__global__ __launch_bounds__(256)
void mlp_tmp_kernel(const float* __restrict__ edges,
                    const float* __restrict__ feats,
                    const float* __restrict__ basis,
                    const float* __restrict__ W1, const float* __restrict__ b1,
                    const float* __restrict__ g1, const float* __restrict__ beta1,
                    const float* __restrict__ W2, const float* __restrict__ b2,
                    const float* __restrict__ g2, const float* __restrict__ beta2,
                    int E)
{
    __shared__ float W1s[32 * 64];
    __shared__ float W2s[64 * 64];
    __shared__ float hst[8][64];
    int tid = threadIdx.x;
    for (int i = tid; i < 32 * 64; i += 256) W1s[i] = W1[i];
    for (int i = tid; i < 64 * 64; i += 256) W2s[i] = W2[i];
    __syncthreads();

    int warp = tid >> 5, lane = tid & 31;
    int e = blockIdx.x * 8 + warp;
    if (e >= E) return;
    const unsigned FULL = 0xffffffffu;

    float xv = edges[(size_t)e * 32 + lane];
    float t0 = b1[lane], t1 = b1[lane + 32];
    #pragma unroll
    for (int k = 0; k < 32; k++) {
        float xk = __shfl_sync(FULL, xv, k);
        t0 = fmaf(xk, W1s[k * 64 + lane], t0);
        t1 = fmaf(xk, W1s[k * 64 + lane + 32], t1);
    }
    float s = t0 + t1, sq = t0 * t0 + t1 * t1;
    #pragma unroll
    for (int o = 16; o > 0; o >>= 1) {
        s += __shfl_xor_sync(FULL, s, o);
        sq += __shfl_xor_sync(FULL, sq, o);
    }
    float mean = s * (1.0f / 64.0f);
    float var = sq * (1.0f / 64.0f) - mean * mean;
    float rstd = rsqrtf(var + 1e-5f);
    float h0 = gelu_exact((t0 - mean) * rstd * g1[lane] + beta1[lane]);
    float h1 = gelu_exact((t1 - mean) * rstd * g1[lane + 32] + beta1[lane + 32]);

    t0 = b2[lane]; t1 = b2[lane + 32];
    #pragma unroll
    for (int k = 0; k < 32; k++) {
        float a = __shfl_sync(FULL, h0, k);
        float b = __shfl_sync(FULL, h1, k);
        t0 = fmaf(a, W2s[k * 64 + lane], t0);
        t0 = fmaf(b, W2s[(k + 32) * 64 + lane], t0);
        t1 = fmaf(a, W2s[k * 64 + lane + 32], t1);
        t1 = fmaf(b, W2s[(k + 32) * 64 + lane + 32], t1);
    }
    s = t0 + t1; sq = t0 * t0 + t1 * t1;
    #pragma unroll
    for (int o = 16; o > 0; o >>= 1) {
        s += __shfl_xor_sync(FULL, s, o);
        sq += __shfl_xor_sync(FULL, sq, o);
    }
    mean = s * (1.0f / 64.0f);
    var = sq * (1.0f / 64.0f) - mean * mean;
    rstd = rsqrtf(var + 1e-5f);
    float o0 = gelu_exact((t0 - mean) * rstd * g2[lane] + beta2[lane]);
    float o1 = gelu_exact((t1 - mean) * rstd * g2[lane + 32] + beta2[lane + 32]);

    // regroup to k-pairs, split hi/lo, write swizzled A image
    hst[warp][lane] = o0; hst[warp][lane + 32] = o1;
    __syncwarp();
    float va = hst[warp][2 * lane], vb = hst[warp][2 * lane + 1];
    __nv_bfloat16 ah = __float2bfloat16(va);
    __nv_bfloat16 al = __float2bfloat16(va - __bfloat162float(ah));
    __nv_bfloat16 bh = __float2bfloat16(vb);
    __nv_bfloat16 bl = __float2bfloat16(vb - __bfloat162float(bh));
    unsigned hp = ((unsigned)*(unsigned short*)&bh << 16) | *(unsigned short*)&ah;
    unsigned lp = ((unsigned)*(unsigned short*)&bl << 16) | *(unsigned short*)&al;
    {
        int row = e & 31;
        unsigned* img = g_aimg + (size_t)(e >> 5) * 2048 + row * 64;
        int ih = lane, il = 32 + lane;      // logical b32 indices (xh, xl)
        int ph = (((ih >> 2) ^ (row & 7)) << 2) | (ih & 3);
        int pl = (((il >> 2) ^ (row & 7)) << 2) | (il & 3);
        img[ph] = hp;
        img[pl] = lp;
    }

    // tmp[e][m*96 + i*3 + f] fp32
    const float* fp = feats + (size_t)e * 96 + lane * 3;
    float f0 = fp[0], f1 = fp[1], f2 = fp[2];
    const float* bp = basis + (size_t)e * 27;
    float* tr = g_tmp + (size_t)e * 288;
    #pragma unroll
    for (int f = 0; f < 3; f++)
        #pragma unroll
        for (int m = 0; m < 3; m++) {
            int q = f * 3 + m;
            tr[m * 96 + lane * 3 + f] = f0 * bp[q] + f1 * bp[9 + q] + f2 * bp[18 + q];
        }
}

// ---------------------------------------------------------------------------
// Prep: W3 bf16 split -> swizzled B images ([wh|wl] per 384-col slab)
// ---------------------------------------------------------------------------
__global__ __launch_bounds__(256)
void w3split_kernel(const float* __restrict__ W3)
{
    int idx = blockIdx.x * 256 + threadIdx.x;
    if (idx >= 3072 * 64) return;
    int n = idx >> 6, c = idx & 63;
    float w = W3[(size_t)c * 3072 + n];
    __nv_bfloat16 wh = __float2bfloat16(w);
    __nv_bfloat16 wl = __float2bfloat16(w - __bfloat162float(wh));
    int slab = n / 384, r = n - slab * 384;
    unsigned char* img = g_b + (size_t)slab * 98304 + r * 256;
    int bh = 2 * c, blo = 128 + 2 * c;
    int ph = (((bh >> 4) ^ (r & 7)) << 4) | (bh & 15);
    int pl = (((blo >> 4) ^ (r & 7)) << 4) | (blo & 15);
    *(unsigned short*)(img + ph) = *(unsigned short*)&wh;
    *(unsigned short*)(img + pl) = *(unsigned short*)&wl;
}

// ---------------------------------------------------------------------------
// Kernel 2: persistent warp-MMA GEMM, B fragments hoisted, direct fragment
// contraction with tmp loaded STRAIGHT FROM GMEM (__ldg; 4 channel-warps share
// addresses -> L1 broadcast). No tmp smem staging, single cp group per tile.
// grid (18 stripes, 8 slabs), 384 thr = 12 warps.
// smem: B[98304] | A x2 [16384] | part[4608] = 119296 B
// ---------------------------------------------------------------------------
#define B_OFF    0
#define A_OFF    98304
#define PART_OFF 114688
#define SMEM_SZ  119296

__global__ __launch_bounds__(384, 1)
void hmma_rw_kernel(float* __restrict__ out, int E)
{
    extern __shared__ unsigned char sm[];
    const int tid = threadIdx.x;
    const int warp = tid >> 5, lane = tid & 31;
    const int slab = blockIdx.y;
    const int tiles = (E + 31) >> 5;
    const unsigned FULL = 0xffffffffu;

    float* part = (float*)(sm + PART_OFF);

    // GEMM warp mapping: 32 edges x 32 cols per warp
    const int n0 = warp * 32;             // col base (within 384)
    const int jb = (warp % 3) * 32;       // j-slice base within channel
    // ldmatrix lane address components (validated R9/R11)
    const int ar  = (lane & 7) + ((lane >> 3) & 1) * 8;   // + mt*16 = A row
    const int akh = (lane >> 4) & 1;                       // A k-half
    const int brow0 = n0 + ((lane >> 4) & 1) * 8 + (lane & 7);
    const int bkh = (lane >> 3) & 1;
    // fragment (row, col) mapping for contraction
    const int r0 = lane >> 2;             // + mt*16 (+8 for d2/d3)
    const int c0 = (lane & 3) * 2;        // + nf*8 within warp's 32 cols
    // final-output mapping: 384 = 3m x 32e x 4ch
    const int fm = tid % 3;
    const int fe = (tid / 3) & 31;
    const int fc = tid / 96;

    const unsigned sA0 = smem_u32(sm + A_OFF);
    const unsigned sB  = smem_u32(sm + B_OFF);

    // ---- prologue: B slab + A(t0), one cp.async group ----
    {
        const unsigned char* src = g_b + (size_t)slab * 98304;
        for (int q = tid; q < 6144; q += 384) cp16(sm + B_OFF + q * 16, src + q * 16);
        int t0 = blockIdx.x;
        if (t0 < tiles) {
            const unsigned* a = g_aimg + (size_t)t0 * 2048;
            for (int q = tid; q < 512; q += 384) cp16(sm + A_OFF + q * 16, a + q * 4);
        }
        cp_commit();
    }
    cp_wait<0>();
    __syncthreads();

    // ---- hoist: load ALL B fragments once (B slab is tile-invariant) ----
    unsigned bw[4][2][4], bl[4][2][4];
    #pragma unroll
    for (int ks = 0; ks < 4; ks++) {
        int chunk = ks * 2 + bkh;
        #pragma unroll
        for (int nf2 = 0; nf2 < 2; nf2++) {
            int brow = brow0 + nf2 * 16;
            unsigned bd = sB + brow * 256 + ((chunk ^ (brow & 7)) << 4);
            ldsm4(bw[ks][nf2], bd);        // wh
            ldsm4(bl[ks][nf2], bd + 128);  // wl
        }
    }

    int par = 0;

    for (int tt = blockIdx.x; tt < tiles; tt += NSTRIPES) {
        // single cp group: A(tt + NSTRIPES) into other buffer
        {
            int tn = tt + NSTRIPES;
            if (tn < tiles) {
                const unsigned* a = g_aimg + (size_t)tn * 2048;
                unsigned char* dst = sm + A_OFF + (par ^ 1) * 8192;
                for (int q = tid; q < 512; q += 384) cp16(dst + q * 16, a + q * 4);
            }
            cp_commit();
        }

        // ---- GEMM: warp computes rw[32e][32c] in registers ----
        const unsigned sA = sA0 + par * 8192;
        float acc[2][4][4];
        #pragma unroll
        for (int mt = 0; mt < 2; mt++)
            #pragma unroll
            for (int nf = 0; nf < 4; nf++)
                #pragma unroll
                for (int j = 0; j < 4; j++) acc[mt][nf][j] = 0.0f;

        #pragma unroll
        for (int ks = 0; ks < 4; ks++) {
            unsigned ah[2][4], al[2][4];
            int chunk = ks * 2 + akh;
            #pragma unroll
            for (int mt = 0; mt < 2; mt++) {
                int row = mt * 16 + ar;
                unsigned ad = sA + row * 256 + ((chunk ^ (row & 7)) << 4);
                ldsm4(ah[mt], ad);         // xh
                ldsm4(al[mt], ad + 128);   // xl
            }
            #pragma unroll
            for (int mt = 0; mt < 2; mt++)
                #pragma unroll
                for (int nf2 = 0; nf2 < 2; nf2++)
                    #pragma unroll
                    for (int hf = 0; hf < 2; hf++) {
                        int nf = nf2 * 2 + hf;
                        mma16816(acc[mt][nf], ah[mt], bw[ks][nf2] + hf * 2); // xh*wh
                        mma16816(acc[mt][nf], al[mt], bw[ks][nf2] + hf * 2); // xl*wh
                        mma16816(acc[mt][nf], ah[mt], bl[ks][nf2] + hf * 2); // xh*wl
                    }
        }

        // ---- direct contraction from fragments; tmp straight from gmem ----
        // warps {w, w+3, w+6, w+9} read identical addresses -> L1 broadcast
        const float* tbase = g_tmp + (size_t)(tt * 32) * 288;
        float p[4][3];
        #pragma unroll
        for (int i = 0; i < 4; i++)
            #pragma unroll
            for (int m = 0; m < 3; m++) p[i][m] = 0.0f;

        #pragma unroll
        for (int mt = 0; mt < 2; mt++)
            #pragma unroll
            for (int rh = 0; rh < 2; rh++) {
                int row = mt * 16 + rh * 8 + r0;
                const float* trow = tbase + row * 288;
                int idx = mt * 2 + rh;
                #pragma unroll
                for (int nf = 0; nf < 4; nf++) {
                    float vx = acc[mt][nf][rh * 2 + 0];
                    float vy = acc[mt][nf][rh * 2 + 1];
                    int j = jb + nf * 8 + c0;
                    #pragma unroll
                    for (int m = 0; m < 3; m++) {
                        float2 t2 = __ldg((const float2*)(trow + m * 96 + j));
                        p[idx][m] = fmaf(vx, t2.x, p[idx][m]);
                        p[idx][m] = fmaf(vy, t2.y, p[idx][m]);
                    }
                }
            }

        // reduce partials over lane&3 (4 lanes hold different col-slices)
        #pragma unroll
        for (int i = 0; i < 4; i++)
            #pragma unroll
            for (int m = 0; m < 3; m++) {
                p[i][m] += __shfl_xor_sync(FULL, p[i][m], 1);
                p[i][m] += __shfl_xor_sync(FULL, p[i][m], 2);
            }
        if ((lane & 3) == 0) {
            #pragma unroll
            for (int mt = 0; mt < 2; mt++)
                #pragma unroll
                for (int rh = 0; rh < 2; rh++) {
                    int row = mt * 16 + rh * 8 + r0;
                    int idx = mt * 2 + rh;
                    #pragma unroll
                    for (int m = 0; m < 3; m++)
                        part[warp * 96 + row * 3 + m] = p[idx][m];
                }
        }
        __syncthreads();

        // ---- final reduce over 3 j-slices + store ----
        {
            int base = fe * 3 + fm;
            float v = part[(fc * 3 + 0) * 96 + base]
                    + part[(fc * 3 + 1) * 96 + base]
                    + part[(fc * 3 + 2) * 96 + base];
            int e = tt * 32 + fe;
            if (e < E)
                out[(size_t)e * 96 + (slab * 4 + fc) * 3 + fm] = v;
        }

        cp_wait<0>();     // next A landed
        __syncthreads();  // part/A reads done before next tile overwrites
        par ^= 1;
    }
}

// ---------------------------------------------------------------------------
extern "C" void kernel_launch(void* const* d_in, const int* in_sizes, int n_in,
                              void* d_out, int out_size)
{
    const float* edges = (const float*)d_in[0];
    const float* feats = (const float*)d_in[1];
    const float* basis = (const float*)d_in[2];
    const float* W1    = (const float*)d_in[3];
    const float* b1    = (const float*)d_in[4];
    const float* g1    = (const float*)d_in[5];
    const float* beta1 = (const float*)d_in[6];
    const float* W2    = (const float*)d_in[7];
    const float* b2    = (const float*)d_in[8];
    const float* g2    = (const float*)d_in[9];
    const float* beta2 = (const float*)d_in[10];
    const float* W3    = (const float*)d_in[11];
    float* out = (float*)d_out;

    int E = in_sizes[0] / 32;
    if (E > E_MAX) E = E_MAX;

    w3split_kernel<<<768, 256>>>(W3);
    mlp_tmp_kernel<<<(E + 7) / 8, 256>>>(edges, feats, basis,
                                         W1, b1, g1, beta1,
                                         W2, b2, g2, beta2, E);

    static bool attr_set = false;
    if (!attr_set) {
        cudaFuncSetAttribute(hmma_rw_kernel,
                             cudaFuncAttributeMaxDynamicSharedMemorySize, SMEM_SZ);
        attr_set = true;
    }
    dim3 grid(NSTRIPES, 8);
    hmma_rw_kernel<<<grid, 384, SMEM_SZ>>>(out, E);
}